// round 2
// baseline (speedup 1.0000x reference)
#include <cuda_runtime.h>
#include <cuda_bf16.h>
#include <float.h>
#include <math.h>

#define NUM_CLASSES 13
#define C1 (NUM_CLASSES + 1)   // 14
#define Bn 64
#define Qn 900
#define Tn 128
#define NT 256
#define NTH 128                // hungarian threads (4 warps)

// ---- scratch (static device globals; no allocation allowed) ----
__device__ float  g_cost[Bn * Tn * Qn];   // cost[b][t][q]
__device__ float  g_lse[Bn * Qn];         // logsumexp per (b,q)
__device__ int    g_pred[Bn * Tn];        // query index assigned to target t
__device__ double g_partial[Bn];          // per-image loss
__device__ int    g_ctr = 0;              // completion counter (restored to 0 each run)

// ============================================================================
// 1) Cost matrix: C[b][t][q] = -softmax(pc[b,q])[label[b,t]] + L1(pb[b,q], tb[b,t])
// ============================================================================
__global__ __launch_bounds__(NT) void cost_kernel(
    const float* __restrict__ pc,   // [B,Q,14]
    const float* __restrict__ pb,   // [B,Q,4]
    const int*   __restrict__ lab,  // [B,T]
    const float* __restrict__ tb)   // [B,T,4]
{
    int b = blockIdx.y;
    int q = blockIdx.x * blockDim.x + threadIdx.x;

    __shared__ float s_tb[Tn * 4];
    __shared__ int   s_lab[Tn];
    for (int i = threadIdx.x; i < Tn * 4; i += NT) s_tb[i] = tb[b * Tn * 4 + i];
    for (int i = threadIdx.x; i < Tn; i += NT)     s_lab[i] = lab[b * Tn + i];
    __syncthreads();
    if (q >= Qn) return;

    const float* lg = pc + (size_t)(b * Qn + q) * C1;
    float m = lg[0];
    #pragma unroll
    for (int c = 1; c < C1; c++) m = fmaxf(m, lg[c]);
    float e[C1]; float se = 0.f;
    #pragma unroll
    for (int c = 0; c < C1; c++) { e[c] = __expf(lg[c] - m); se += e[c]; }
    float inv = 1.0f / se;
    g_lse[b * Qn + q] = m + logf(se);

    const float4 pbq = *reinterpret_cast<const float4*>(pb + (size_t)(b * Qn + q) * 4);

    float* crow = g_cost + (size_t)b * Tn * Qn + q;
    #pragma unroll 4
    for (int t = 0; t < Tn; t++) {
        float cb = fabsf(pbq.x - s_tb[t * 4 + 0]) + fabsf(pbq.y - s_tb[t * 4 + 1])
                 + fabsf(pbq.z - s_tb[t * 4 + 2]) + fabsf(pbq.w - s_tb[t * 4 + 3]);
        float cc = -e[s_lab[t]] * inv;
        crow[(size_t)t * Qn] = cb + cc;
    }
}

// ============================================================================
// 2) Hungarian (Jonker-Volgenant) with DEFERRED dual updates.
//    One CTA (128 threads) per image. rows = 128 targets, cols = 900 queries.
//    Per inner iteration: one row-scan + warp-shuffle argmin + 2 barriers.
//    No O(Q) dual-update loop per iteration: duals applied once per phase
//    from (C_final - tu[j]).
// ============================================================================
__global__ __launch_bounds__(NTH) void hungarian_kernel()
{
    int b = blockIdx.x;
    int tid = threadIdx.x;
    int lane = tid & 31, warp = tid >> 5;

    __shared__ double u[Tn + 1];
    __shared__ double v[Qn + 1];
    __shared__ double minv[Qn + 1];   // minv_abs = minv_true + C
    __shared__ double tu[Qn + 1];     // C at the moment column became used
    __shared__ int    way[Qn + 1];
    __shared__ int    p[Qn + 1];
    __shared__ unsigned char used[Qn + 1];
    __shared__ double s_wv[NTH / 32];
    __shared__ int    s_wi[NTH / 32];
    __shared__ int    s_j0, s_i0, s_done;
    __shared__ double s_C;

    for (int j = tid; j <= Qn; j += NTH) { v[j] = 0.0; p[j] = 0; minv[j] = DBL_MAX; used[j] = 0; }
    for (int i = tid; i <= Tn; i += NTH) u[i] = 0.0;
    __syncthreads();

    const float* cost = g_cost + (size_t)b * Tn * Qn;

    for (int i = 1; i <= Tn; i++) {
        if (tid == 0) {
            p[0] = i; s_j0 = 0; s_i0 = i; s_C = 0.0; s_done = 0;
            used[0] = 1; tu[0] = 0.0;
        }
        __syncthreads();

        while (true) {
            int i0 = s_i0, j0 = s_j0;
            double aC = u[i0] - s_C;          // r = cost - u_base - v_base + C
            const float* crow = cost + (size_t)(i0 - 1) * Qn;

            double lv = DBL_MAX; int li = Qn + 1;
            for (int j = tid + 1; j <= Qn; j += NTH) {
                if (!used[j]) {
                    double r = (double)crow[j - 1] - aC - v[j];
                    double mv = minv[j];
                    if (r < mv) { mv = r; minv[j] = r; way[j] = j0; }
                    if (mv < lv) { lv = mv; li = j; }   // ascending j => first idx kept
                }
            }
            // warp-level argmin (value, lowest index on tie)
            #pragma unroll
            for (int s = 16; s; s >>= 1) {
                double ov = __shfl_down_sync(0xffffffffu, lv, s);
                int    oi = __shfl_down_sync(0xffffffffu, li, s);
                if (ov < lv || (ov == lv && oi < li)) { lv = ov; li = oi; }
            }
            if (lane == 0) { s_wv[warp] = lv; s_wi[warp] = li; }
            __syncthreads();
            if (tid == 0) {
                double bv = s_wv[0]; int bi = s_wi[0];
                #pragma unroll
                for (int w = 1; w < NTH / 32; w++) {
                    double ov = s_wv[w]; int oi = s_wi[w];
                    if (ov < bv || (ov == bv && oi < bi)) { bv = ov; bi = oi; }
                }
                s_j0 = bi; s_C = bv;          // C += delta  (bv = minv_abs[j1])
                if (p[bi] == 0) s_done = 1;
                else { used[bi] = 1; tu[bi] = bv; s_i0 = p[bi]; }
            }
            __syncthreads();
            if (s_done) break;
        }

        // apply duals (p BEFORE augmentation) + reset state for next phase
        double Cf = s_C;
        for (int j = tid; j <= Qn; j += NTH) {
            if (used[j]) {
                double dv = Cf - tu[j];
                v[j] -= dv;              // v[0] dummy, never read
                u[p[j]] += dv;           // includes u[i] via p[0]=i
                used[j] = 0;
            }
            minv[j] = DBL_MAX;
        }
        __syncthreads();
        if (tid == 0) {                  // augment along alternating path
            int j0 = s_j0;
            while (j0) { int j1 = way[j0]; p[j0] = p[j1]; j0 = j1; }
        }
        __syncthreads();
    }

    for (int j = tid + 1; j <= Qn; j += NTH) {
        int pi = p[j];
        if (pi > 0) g_pred[b * Tn + pi - 1] = j - 1;
    }
}

// ============================================================================
// 3) Per-image loss + last-block global reduction (fused finalize)
// ============================================================================
__global__ __launch_bounds__(NT) void loss_kernel(
    const float* __restrict__ pc,
    const float* __restrict__ pb,
    const int*   __restrict__ lab,
    const float* __restrict__ tb,
    float* __restrict__ out)
{
    int b = blockIdx.x;
    int tid = threadIdx.x;
    __shared__ int tcl[Qn];
    __shared__ double sred[NT];
    __shared__ int s_last;

    double l1 = 0.0, gsum = 0.0;
    if (tid < Tn) {
        int t = tid;
        int qi = g_pred[b * Tn + t];
        const float4 P = *reinterpret_cast<const float4*>(pb + (size_t)(b * Qn + qi) * 4);
        const float4 G = *reinterpret_cast<const float4*>(tb + (size_t)(b * Tn + t) * 4);
        double px = P.x, py = P.y, pw = P.z, ph = P.w;
        double gx = G.x, gy = G.y, gw = G.z, gh = G.w;
        l1 = fabs(px - gx) + fabs(py - gy) + fabs(pw - gw) + fabs(ph - gh);

        double p0 = px - 0.5 * pw, p1 = py - 0.5 * ph, p2 = px + 0.5 * pw, p3 = py + 0.5 * ph;
        double g0 = gx - 0.5 * gw, g1 = gy - 0.5 * gh, g2 = gx + 0.5 * gw, g3 = gy + 0.5 * gh;
        double a1 = (p2 - p0) * (p3 - p1);
        double a2 = (g2 - g0) * (g3 - g1);
        double iw = fmin(p2, g2) - fmax(p0, g0); iw = iw > 0.0 ? iw : 0.0;
        double ih = fmin(p3, g3) - fmax(p1, g1); ih = ih > 0.0 ? ih : 0.0;
        double inter = iw * ih;
        double uni = a1 + a2 - inter;
        double iou = inter / uni;
        double cw = fmax(p2, g2) - fmin(p0, g0);
        double ch = fmax(p3, g3) - fmin(p1, g1);
        double ac = cw * ch;
        double giou = iou - (ac - uni) / ac;
        gsum = 1.0 - giou;
    }

    for (int q = tid; q < Qn; q += NT) tcl[q] = NUM_CLASSES;
    __syncthreads();
    if (tid < Tn) tcl[g_pred[b * Tn + tid]] = lab[b * Tn + tid];
    __syncthreads();

    double wn = 0.0, ws = 0.0;
    for (int q = tid; q < Qn; q += NT) {
        int c = tcl[q];
        double w = (c == NUM_CLASSES) ? 0.05 : 1.0;
        double nll = (double)g_lse[b * Qn + q] - (double)pc[(size_t)(b * Qn + q) * C1 + c];
        wn += w * nll; ws += w;
    }

    // block-reduce 4 quantities
    sred[tid] = l1;   __syncthreads();
    for (int s = NT / 2; s; s >>= 1) { if (tid < s) sred[tid] += sred[tid + s]; __syncthreads(); }
    double l1t = sred[0]; __syncthreads();
    sred[tid] = gsum; __syncthreads();
    for (int s = NT / 2; s; s >>= 1) { if (tid < s) sred[tid] += sred[tid + s]; __syncthreads(); }
    double gst = sred[0]; __syncthreads();
    sred[tid] = wn;   __syncthreads();
    for (int s = NT / 2; s; s >>= 1) { if (tid < s) sred[tid] += sred[tid + s]; __syncthreads(); }
    double wnt = sred[0]; __syncthreads();
    sred[tid] = ws;   __syncthreads();
    for (int s = NT / 2; s; s >>= 1) { if (tid < s) sred[tid] += sred[tid + s]; __syncthreads(); }
    double wst = sred[0]; __syncthreads();

    if (tid == 0) {
        double bbox = 5.0 * (l1t / (Tn * 4.0)) + 2.0 * (gst / Tn);
        g_partial[b] = bbox + wnt / wst;
        __threadfence();
        int t = atomicAdd(&g_ctr, 1);
        s_last = (t == Bn - 1);
    }
    __syncthreads();

    if (s_last) {
        double val = (tid < Bn) ? ((volatile double*)g_partial)[tid] : 0.0;
        sred[tid] = val; __syncthreads();
        for (int s = NT / 2; s; s >>= 1) { if (tid < s) sred[tid] += sred[tid + s]; __syncthreads(); }
        if (tid == 0) {
            out[0] = (float)(sred[0] / (double)(Bn * Tn));
            g_ctr = 0;                      // restore for next graph replay
        }
    }
}

extern "C" void kernel_launch(void* const* d_in, const int* in_sizes, int n_in,
                              void* d_out, int out_size)
{
    const float* pc  = (const float*)d_in[0];   // predicted_class [64,900,14]
    const float* pb  = (const float*)d_in[1];   // predicted_bbox  [64,900,4]
    const int*   lab = (const int*)  d_in[2];   // target_labels   [64,128]
    const float* tb  = (const float*)d_in[3];   // target_boxes    [64,128,4]
    float* out = (float*)d_out;

    dim3 cgrid((Qn + NT - 1) / NT, Bn);
    cost_kernel<<<cgrid, NT>>>(pc, pb, lab, tb);
    hungarian_kernel<<<Bn, NTH>>>();
    loss_kernel<<<Bn, NT>>>(pc, pb, lab, tb, out);
}

// round 3
// speedup vs baseline: 3.3145x; 3.3145x over previous
#include <cuda_runtime.h>
#include <cuda_bf16.h>
#include <float.h>
#include <math.h>

#define NUM_CLASSES 13
#define C1 (NUM_CLASSES + 1)   // 14
#define Bn 64
#define Qn 900
#define Tn 128
#define NT 256
#define NTH 256                // hungarian threads (8 warps)
#define NWARP (NTH / 32)

// ---- scratch (static device globals; no allocation allowed) ----
__device__ float  g_cost[Bn * Tn * Qn];   // cost[b][t][q]
__device__ float  g_lse[Bn * Qn];         // logsumexp per (b,q)
__device__ int    g_pred[Bn * Tn];        // query index assigned to target t
__device__ double g_partial[Bn];          // per-image loss
__device__ int    g_ctr = 0;              // completion counter (reset each run)

// ============================================================================
// 1) Cost matrix: C[b][t][q] = -softmax(pc[b,q])[label[b,t]] + L1(pb[b,q], tb[b,t])
// ============================================================================
__global__ __launch_bounds__(NT) void cost_kernel(
    const float* __restrict__ pc,   // [B,Q,14]
    const float* __restrict__ pb,   // [B,Q,4]
    const int*   __restrict__ lab,  // [B,T]
    const float* __restrict__ tb)   // [B,T,4]
{
    int b = blockIdx.y;
    int q = blockIdx.x * blockDim.x + threadIdx.x;

    __shared__ float s_tb[Tn * 4];
    __shared__ int   s_lab[Tn];
    for (int i = threadIdx.x; i < Tn * 4; i += NT) s_tb[i] = tb[b * Tn * 4 + i];
    for (int i = threadIdx.x; i < Tn; i += NT)     s_lab[i] = lab[b * Tn + i];
    __syncthreads();
    if (q >= Qn) return;

    const float* lg = pc + (size_t)(b * Qn + q) * C1;
    float m = lg[0];
    #pragma unroll
    for (int c = 1; c < C1; c++) m = fmaxf(m, lg[c]);
    float e[C1]; float se = 0.f;
    #pragma unroll
    for (int c = 0; c < C1; c++) { e[c] = __expf(lg[c] - m); se += e[c]; }
    float inv = 1.0f / se;
    g_lse[b * Qn + q] = m + logf(se);

    const float4 pbq = *reinterpret_cast<const float4*>(pb + (size_t)(b * Qn + q) * 4);

    float* crow = g_cost + (size_t)b * Tn * Qn + q;
    #pragma unroll 4
    for (int t = 0; t < Tn; t++) {
        float cb = fabsf(pbq.x - s_tb[t * 4 + 0]) + fabsf(pbq.y - s_tb[t * 4 + 1])
                 + fabsf(pbq.z - s_tb[t * 4 + 2]) + fabsf(pbq.w - s_tb[t * 4 + 3]);
        float cc = -e[s_lab[t]] * inv;
        crow[(size_t)t * Qn] = cb + cc;
    }
}

// ============================================================================
// 2) Hungarian (Jonker-Volgenant), deferred duals, FLOAT arithmetic.
//    One CTA (256 threads) per image; rows = 128 targets, cols = 900 queries.
//    Float is safe: JV returns the optimal assignment (a property of the cost
//    matrix, not of the arithmetic path); 1e-6 rounding can at worst swap a
//    near-tied pair, perturbing the final scalar ~1e-5 rel.
// ============================================================================
__global__ __launch_bounds__(NTH) void hungarian_kernel()
{
    int b = blockIdx.x;
    int tid = threadIdx.x;
    int lane = tid & 31, warp = tid >> 5;

    __shared__ float u[Tn + 1];
    __shared__ float v[Qn + 1];
    __shared__ float minv[Qn + 1];   // minv_abs = minv_true + C
    __shared__ float tu[Qn + 1];     // C at the moment column became used
    __shared__ int   way[Qn + 1];
    __shared__ int   p[Qn + 1];
    __shared__ unsigned char used[Qn + 1];
    __shared__ float s_wv[NWARP];
    __shared__ int   s_wi[NWARP];
    __shared__ int   s_j0, s_i0, s_done;
    __shared__ float s_C;

    for (int j = tid; j <= Qn; j += NTH) { v[j] = 0.f; p[j] = 0; minv[j] = FLT_MAX; used[j] = 0; }
    for (int i = tid; i <= Tn; i += NTH) u[i] = 0.f;
    __syncthreads();

    const float* cost = g_cost + (size_t)b * Tn * Qn;

    // per-thread column slots: j = 1 + tid + k*NTH
    int  js[4]; bool valid[4];
    #pragma unroll
    for (int k = 0; k < 4; k++) { js[k] = 1 + tid + k * NTH; valid[k] = (js[k] <= Qn); }

    for (int i = 1; i <= Tn; i++) {
        if (tid == 0) {
            p[0] = i; s_j0 = 0; s_i0 = i; s_C = 0.f; s_done = 0;
            used[0] = 1; tu[0] = 0.f;
        }
        __syncthreads();

        while (true) {
            int i0 = s_i0, j0 = s_j0;
            float aC = u[i0] - s_C;          // r = cost - u_base - v_base + C
            const float* crow = cost + (size_t)(i0 - 1) * Qn;

            // front-batch the 4 global loads (one L2 round trip)
            float cr[4];
            #pragma unroll
            for (int k = 0; k < 4; k++)
                cr[k] = valid[k] ? __ldg(crow + js[k] - 1) : 0.f;

            float lv = FLT_MAX; int li = Qn + 1;
            #pragma unroll
            for (int k = 0; k < 4; k++) {
                int j = js[k];
                if (valid[k] && !used[j]) {
                    float r = cr[k] - aC - v[j];
                    float mv = minv[j];
                    if (r < mv) { mv = r; minv[j] = r; way[j] = j0; }
                    if (mv < lv || (mv == lv && j < li)) { lv = mv; li = j; }
                }
            }
            // warp argmin (float, lowest index on tie)
            #pragma unroll
            for (int s = 16; s; s >>= 1) {
                float ov = __shfl_down_sync(0xffffffffu, lv, s);
                int   oi = __shfl_down_sync(0xffffffffu, li, s);
                if (ov < lv || (ov == lv && oi < li)) { lv = ov; li = oi; }
            }
            if (lane == 0) { s_wv[warp] = lv; s_wi[warp] = li; }
            __syncthreads();

            if (warp == 0) {
                float bv = (lane < NWARP) ? s_wv[lane] : FLT_MAX;
                int   bi = (lane < NWARP) ? s_wi[lane] : Qn + 1;
                #pragma unroll
                for (int s = NWARP / 2; s; s >>= 1) {
                    float ov = __shfl_down_sync(0xffffffffu, bv, s, NWARP);
                    int   oi = __shfl_down_sync(0xffffffffu, bi, s, NWARP);
                    if (ov < bv || (ov == bv && oi < bi)) { bv = ov; bi = oi; }
                }
                if (lane == 0) {
                    s_j0 = bi; s_C = bv;      // C += delta
                    if (p[bi] == 0) s_done = 1;
                    else { used[bi] = 1; tu[bi] = bv; s_i0 = p[bi]; }
                }
            }
            __syncthreads();
            if (s_done) break;
        }

        // apply duals (p BEFORE augmentation) + reset state for next phase
        float Cf = s_C;
        for (int j = tid; j <= Qn; j += NTH) {
            if (used[j]) {
                float dv = Cf - tu[j];
                v[j] -= dv;              // v[0] dummy, never read
                u[p[j]] += dv;           // includes u[i] via p[0]=i
                used[j] = 0;
            }
            minv[j] = FLT_MAX;
        }
        __syncthreads();
        if (tid == 0) {                  // augment along alternating path
            int j0 = s_j0;
            while (j0) { int j1 = way[j0]; p[j0] = p[j1]; j0 = j1; }
        }
        __syncthreads();
    }

    for (int j = tid + 1; j <= Qn; j += NTH) {
        int pi = p[j];
        if (pi > 0) g_pred[b * Tn + pi - 1] = j - 1;
    }
}

// ============================================================================
// 3) Per-image loss + last-block global reduction (fused finalize)
// ============================================================================
__global__ __launch_bounds__(NT) void loss_kernel(
    const float* __restrict__ pc,
    const float* __restrict__ pb,
    const int*   __restrict__ lab,
    const float* __restrict__ tb,
    float* __restrict__ out)
{
    int b = blockIdx.x;
    int tid = threadIdx.x;
    __shared__ int tcl[Qn];
    __shared__ double sred[NT];
    __shared__ int s_last;

    double l1 = 0.0, gsum = 0.0;
    if (tid < Tn) {
        int t = tid;
        int qi = g_pred[b * Tn + t];
        const float4 P = *reinterpret_cast<const float4*>(pb + (size_t)(b * Qn + qi) * 4);
        const float4 G = *reinterpret_cast<const float4*>(tb + (size_t)(b * Tn + t) * 4);
        double px = P.x, py = P.y, pw = P.z, ph = P.w;
        double gx = G.x, gy = G.y, gw = G.z, gh = G.w;
        l1 = fabs(px - gx) + fabs(py - gy) + fabs(pw - gw) + fabs(ph - gh);

        double p0 = px - 0.5 * pw, p1 = py - 0.5 * ph, p2 = px + 0.5 * pw, p3 = py + 0.5 * ph;
        double g0 = gx - 0.5 * gw, g1 = gy - 0.5 * gh, g2 = gx + 0.5 * gw, g3 = gy + 0.5 * gh;
        double a1 = (p2 - p0) * (p3 - p1);
        double a2 = (g2 - g0) * (g3 - g1);
        double iw = fmin(p2, g2) - fmax(p0, g0); iw = iw > 0.0 ? iw : 0.0;
        double ih = fmin(p3, g3) - fmax(p1, g1); ih = ih > 0.0 ? ih : 0.0;
        double inter = iw * ih;
        double uni = a1 + a2 - inter;
        double iou = inter / uni;
        double cw = fmax(p2, g2) - fmin(p0, g0);
        double ch = fmax(p3, g3) - fmin(p1, g1);
        double ac = cw * ch;
        double giou = iou - (ac - uni) / ac;
        gsum = 1.0 - giou;
    }

    for (int q = tid; q < Qn; q += NT) tcl[q] = NUM_CLASSES;
    __syncthreads();
    if (tid < Tn) tcl[g_pred[b * Tn + tid]] = lab[b * Tn + tid];
    __syncthreads();

    double wn = 0.0, ws = 0.0;
    for (int q = tid; q < Qn; q += NT) {
        int c = tcl[q];
        double w = (c == NUM_CLASSES) ? 0.05 : 1.0;
        double nll = (double)g_lse[b * Qn + q] - (double)pc[(size_t)(b * Qn + q) * C1 + c];
        wn += w * nll; ws += w;
    }

    sred[tid] = l1;   __syncthreads();
    for (int s = NT / 2; s; s >>= 1) { if (tid < s) sred[tid] += sred[tid + s]; __syncthreads(); }
    double l1t = sred[0]; __syncthreads();
    sred[tid] = gsum; __syncthreads();
    for (int s = NT / 2; s; s >>= 1) { if (tid < s) sred[tid] += sred[tid + s]; __syncthreads(); }
    double gst = sred[0]; __syncthreads();
    sred[tid] = wn;   __syncthreads();
    for (int s = NT / 2; s; s >>= 1) { if (tid < s) sred[tid] += sred[tid + s]; __syncthreads(); }
    double wnt = sred[0]; __syncthreads();
    sred[tid] = ws;   __syncthreads();
    for (int s = NT / 2; s; s >>= 1) { if (tid < s) sred[tid] += sred[tid + s]; __syncthreads(); }
    double wst = sred[0]; __syncthreads();

    if (tid == 0) {
        double bbox = 5.0 * (l1t / (Tn * 4.0)) + 2.0 * (gst / Tn);
        g_partial[b] = bbox + wnt / wst;
        __threadfence();
        int t = atomicAdd(&g_ctr, 1);
        s_last = (t == Bn - 1);
    }
    __syncthreads();

    if (s_last) {
        double val = (tid < Bn) ? ((volatile double*)g_partial)[tid] : 0.0;
        sred[tid] = val; __syncthreads();
        for (int s = NT / 2; s; s >>= 1) { if (tid < s) sred[tid] += sred[tid + s]; __syncthreads(); }
        if (tid == 0) {
            out[0] = (float)(sred[0] / (double)(Bn * Tn));
            g_ctr = 0;                      // restore for next graph replay
        }
    }
}

extern "C" void kernel_launch(void* const* d_in, const int* in_sizes, int n_in,
                              void* d_out, int out_size)
{
    const float* pc  = (const float*)d_in[0];   // predicted_class [64,900,14]
    const float* pb  = (const float*)d_in[1];   // predicted_bbox  [64,900,4]
    const int*   lab = (const int*)  d_in[2];   // target_labels   [64,128]
    const float* tb  = (const float*)d_in[3];   // target_boxes    [64,128,4]
    float* out = (float*)d_out;

    dim3 cgrid((Qn + NT - 1) / NT, Bn);
    cost_kernel<<<cgrid, NT>>>(pc, pb, lab, tb);
    hungarian_kernel<<<Bn, NTH>>>();
    loss_kernel<<<Bn, NT>>>(pc, pb, lab, tb, out);
}

// round 4
// speedup vs baseline: 4.7942x; 1.4464x over previous
#include <cuda_runtime.h>
#include <cuda_bf16.h>
#include <float.h>
#include <math.h>

#define NUM_CLASSES 13
#define C1 (NUM_CLASSES + 1)   // 14
#define Bn 64
#define Qn 900
#define Tn 128
#define NT 256
#define NTH 256                // hungarian threads (8 warps)
#define NWARP (NTH / 32)
#define JPT 4                  // columns per thread (float4)
#define NACT (Qn / JPT)        // 225 active scan threads

// ---- scratch (static device globals; no allocation allowed) ----
__device__ __align__(256) float g_cost[Bn * Tn * Qn];   // cost[b][t][q]
__device__ float  g_lse[Bn * Qn];         // logsumexp per (b,q)
__device__ int    g_pred[Bn * Tn];        // query index assigned to target t
__device__ double g_partial[Bn];          // per-image loss
__device__ int    g_ctr = 0;              // completion counter (reset each run)

// order-preserving float <-> uint32 (no NaNs in costs)
__device__ __forceinline__ unsigned enc_f(float f) {
    unsigned u = __float_as_uint(f);
    return (u & 0x80000000u) ? ~u : (u | 0x80000000u);
}
__device__ __forceinline__ float dec_f(unsigned e) {
    unsigned x = (e & 0x80000000u) ? (e & 0x7fffffffu) : ~e;
    return __uint_as_float(x);
}

// ============================================================================
// 1) Cost matrix: C[b][t][q] = -softmax(pc[b,q])[label[b,t]] + L1(pb[b,q], tb[b,t])
// ============================================================================
__global__ __launch_bounds__(NT) void cost_kernel(
    const float* __restrict__ pc,   // [B,Q,14]
    const float* __restrict__ pb,   // [B,Q,4]
    const int*   __restrict__ lab,  // [B,T]
    const float* __restrict__ tb)   // [B,T,4]
{
    int b = blockIdx.y;
    int q = blockIdx.x * blockDim.x + threadIdx.x;

    __shared__ float s_tb[Tn * 4];
    __shared__ int   s_lab[Tn];
    for (int i = threadIdx.x; i < Tn * 4; i += NT) s_tb[i] = tb[b * Tn * 4 + i];
    for (int i = threadIdx.x; i < Tn; i += NT)     s_lab[i] = lab[b * Tn + i];
    __syncthreads();
    if (q >= Qn) return;

    const float* lg = pc + (size_t)(b * Qn + q) * C1;
    float m = lg[0];
    #pragma unroll
    for (int c = 1; c < C1; c++) m = fmaxf(m, lg[c]);
    float e[C1]; float se = 0.f;
    #pragma unroll
    for (int c = 0; c < C1; c++) { e[c] = __expf(lg[c] - m); se += e[c]; }
    float inv = 1.0f / se;
    g_lse[b * Qn + q] = m + logf(se);

    const float4 pbq = *reinterpret_cast<const float4*>(pb + (size_t)(b * Qn + q) * 4);

    float* crow = g_cost + (size_t)b * Tn * Qn + q;
    #pragma unroll 4
    for (int t = 0; t < Tn; t++) {
        float cb = fabsf(pbq.x - s_tb[t * 4 + 0]) + fabsf(pbq.y - s_tb[t * 4 + 1])
                 + fabsf(pbq.z - s_tb[t * 4 + 2]) + fabsf(pbq.w - s_tb[t * 4 + 3]);
        float cc = -e[s_lab[t]] * inv;
        crow[(size_t)t * Qn] = cb + cc;
    }
}

// ============================================================================
// 2) Hungarian (JV), deferred duals, float, 1 barrier per inner iteration.
//    One CTA (256 threads) per image; rows = 128 targets, cols = 900 queries.
//    Thread t owns columns 4t+1..4t+4 (one float4 row load per iteration).
// ============================================================================
__global__ __launch_bounds__(NTH) void hungarian_kernel()
{
    int b = blockIdx.x;
    int tid = threadIdx.x;
    int lane = tid & 31, warp = tid >> 5;

    __shared__ float u[Tn + 1];
    __shared__ float v[Qn + 1];
    __shared__ float minv[Qn + 1];   // minv_abs = minv_true + C
    __shared__ float tu[Qn + 1];     // C at the moment column became used
    __shared__ int   way[Qn + 1];
    __shared__ int   p[Qn + 1];
    __shared__ unsigned char used[Qn + 1];
    __shared__ unsigned s_wv[2][NWARP];   // parity-double-buffered warp minima
    __shared__ int      s_wi[2][NWARP];

    for (int j = tid; j <= Qn; j += NTH) { v[j] = 0.f; p[j] = 0; minv[j] = FLT_MAX; used[j] = 0; }
    for (int i = tid; i <= Tn; i += NTH) u[i] = 0.f;
    __syncthreads();

    const float* cost = g_cost + (size_t)b * Tn * Qn;
    const bool valid = (tid < NACT);
    const int  jbase = JPT * tid + 1;     // first owned column (1-based)

    for (int i = 1; i <= Tn; i++) {
        if (tid == 0) { p[0] = i; used[0] = 1; tu[0] = 0.f; }
        __syncthreads();

        int   i0 = i;
        float C  = 0.f;
        int   lastj1 = 0;
        float Cmark = 0.f;
        int   it = 0;
        int   jfinal; float Cf;

        while (true) {
            int par = it & 1;
            // one L2 round trip for this thread's 4 columns of the scanned row
            float4 cr = make_float4(0.f, 0.f, 0.f, 0.f);
            if (valid) cr = __ldg(reinterpret_cast<const float4*>(
                                  cost + (size_t)(i0 - 1) * Qn + (jbase - 1)));
            float aC = u[i0] - C;
            // deferred mark of previous j1 (race-free: scans exclude j==lastj1)
            if (tid == 0 && it > 0) { used[lastj1] = 1; tu[lastj1] = Cmark; }

            unsigned benc = 0xFFFFFFFFu; int bj = 0x7FFFFFFF;
            if (valid) {
                #pragma unroll
                for (int k = 0; k < JPT; k++) {
                    int j = jbase + k;
                    float cv = (&cr.x)[k];
                    if (!used[j] && j != lastj1) {
                        float r = cv - aC - v[j];
                        float mv = minv[j];
                        if (r < mv) { mv = r; minv[j] = r; way[j] = lastj1; }
                        unsigned e = enc_f(mv);
                        if (e < benc) { benc = e; bj = j; }   // ascending j => first kept
                    }
                }
            }
            // warp argmin via two REDUX ops (exact lexicographic (value, j))
            unsigned m = __reduce_min_sync(0xffffffffu, benc);
            int cand = (benc == m) ? bj : 0x7FFFFFFF;
            int jm = __reduce_min_sync(0xffffffffu, cand);
            if (lane == 0) { s_wv[par][warp] = m; s_wi[par][warp] = jm; }
            __syncthreads();

            // every thread reduces the 8 leader slots (no second barrier)
            unsigned ge = s_wv[par][0]; int gj = s_wi[par][0];
            #pragma unroll
            for (int w = 1; w < NWARP; w++) {
                unsigned e2 = s_wv[par][w]; int j2 = s_wi[par][w];
                if (e2 < ge || (e2 == ge && j2 < gj)) { ge = e2; gj = j2; }
            }
            float Cn = dec_f(ge);
            int j1 = gj;
            int i0n = p[j1];
            if (i0n == 0) { jfinal = j1; Cf = Cn; break; }
            Cmark = Cn; lastj1 = j1; C = Cn; i0 = i0n; it++;
        }

        // apply duals (p BEFORE augmentation) + reset state for next phase
        for (int j = tid; j <= Qn; j += NTH) {
            if (used[j]) {
                float dv = Cf - tu[j];
                v[j] -= dv;              // v[0] dummy, never read
                u[p[j]] += dv;           // includes u[i] via p[0]=i
                used[j] = 0;
            }
            minv[j] = FLT_MAX;
        }
        __syncthreads();
        if (tid == 0) {                  // augment along alternating path
            int j0 = jfinal;
            while (j0) { int jp = way[j0]; p[j0] = p[jp]; j0 = jp; }
        }
        __syncthreads();
    }

    for (int j = tid + 1; j <= Qn; j += NTH) {
        int pi = p[j];
        if (pi > 0) g_pred[b * Tn + pi - 1] = j - 1;
    }
}

// ============================================================================
// 3) Per-image loss + last-block global reduction (fused finalize)
// ============================================================================
__global__ __launch_bounds__(NT) void loss_kernel(
    const float* __restrict__ pc,
    const float* __restrict__ pb,
    const int*   __restrict__ lab,
    const float* __restrict__ tb,
    float* __restrict__ out)
{
    int b = blockIdx.x;
    int tid = threadIdx.x;
    __shared__ int tcl[Qn];
    __shared__ double sred[NT];
    __shared__ int s_last;

    double l1 = 0.0, gsum = 0.0;
    if (tid < Tn) {
        int t = tid;
        int qi = g_pred[b * Tn + t];
        const float4 P = *reinterpret_cast<const float4*>(pb + (size_t)(b * Qn + qi) * 4);
        const float4 G = *reinterpret_cast<const float4*>(tb + (size_t)(b * Tn + t) * 4);
        double px = P.x, py = P.y, pw = P.z, ph = P.w;
        double gx = G.x, gy = G.y, gw = G.z, gh = G.w;
        l1 = fabs(px - gx) + fabs(py - gy) + fabs(pw - gw) + fabs(ph - gh);

        double p0 = px - 0.5 * pw, p1 = py - 0.5 * ph, p2 = px + 0.5 * pw, p3 = py + 0.5 * ph;
        double g0 = gx - 0.5 * gw, g1 = gy - 0.5 * gh, g2 = gx + 0.5 * gw, g3 = gy + 0.5 * gh;
        double a1 = (p2 - p0) * (p3 - p1);
        double a2 = (g2 - g0) * (g3 - g1);
        double iw = fmin(p2, g2) - fmax(p0, g0); iw = iw > 0.0 ? iw : 0.0;
        double ih = fmin(p3, g3) - fmax(p1, g1); ih = ih > 0.0 ? ih : 0.0;
        double inter = iw * ih;
        double uni = a1 + a2 - inter;
        double iou = inter / uni;
        double cw = fmax(p2, g2) - fmin(p0, g0);
        double ch = fmax(p3, g3) - fmin(p1, g1);
        double ac = cw * ch;
        double giou = iou - (ac - uni) / ac;
        gsum = 1.0 - giou;
    }

    for (int q = tid; q < Qn; q += NT) tcl[q] = NUM_CLASSES;
    __syncthreads();
    if (tid < Tn) tcl[g_pred[b * Tn + tid]] = lab[b * Tn + tid];
    __syncthreads();

    double wn = 0.0, ws = 0.0;
    for (int q = tid; q < Qn; q += NT) {
        int c = tcl[q];
        double w = (c == NUM_CLASSES) ? 0.05 : 1.0;
        double nll = (double)g_lse[b * Qn + q] - (double)pc[(size_t)(b * Qn + q) * C1 + c];
        wn += w * nll; ws += w;
    }

    sred[tid] = l1;   __syncthreads();
    for (int s = NT / 2; s; s >>= 1) { if (tid < s) sred[tid] += sred[tid + s]; __syncthreads(); }
    double l1t = sred[0]; __syncthreads();
    sred[tid] = gsum; __syncthreads();
    for (int s = NT / 2; s; s >>= 1) { if (tid < s) sred[tid] += sred[tid + s]; __syncthreads(); }
    double gst = sred[0]; __syncthreads();
    sred[tid] = wn;   __syncthreads();
    for (int s = NT / 2; s; s >>= 1) { if (tid < s) sred[tid] += sred[tid + s]; __syncthreads(); }
    double wnt = sred[0]; __syncthreads();
    sred[tid] = ws;   __syncthreads();
    for (int s = NT / 2; s; s >>= 1) { if (tid < s) sred[tid] += sred[tid + s]; __syncthreads(); }
    double wst = sred[0]; __syncthreads();

    if (tid == 0) {
        double bbox = 5.0 * (l1t / (Tn * 4.0)) + 2.0 * (gst / Tn);
        g_partial[b] = bbox + wnt / wst;
        __threadfence();
        int t = atomicAdd(&g_ctr, 1);
        s_last = (t == Bn - 1);
    }
    __syncthreads();

    if (s_last) {
        double val = (tid < Bn) ? ((volatile double*)g_partial)[tid] : 0.0;
        sred[tid] = val; __syncthreads();
        for (int s = NT / 2; s; s >>= 1) { if (tid < s) sred[tid] += sred[tid + s]; __syncthreads(); }
        if (tid == 0) {
            out[0] = (float)(sred[0] / (double)(Bn * Tn));
            g_ctr = 0;                      // restore for next graph replay
        }
    }
}

extern "C" void kernel_launch(void* const* d_in, const int* in_sizes, int n_in,
                              void* d_out, int out_size)
{
    const float* pc  = (const float*)d_in[0];   // predicted_class [64,900,14]
    const float* pb  = (const float*)d_in[1];   // predicted_bbox  [64,900,4]
    const int*   lab = (const int*)  d_in[2];   // target_labels   [64,128]
    const float* tb  = (const float*)d_in[3];   // target_boxes    [64,128,4]
    float* out = (float*)d_out;

    dim3 cgrid((Qn + NT - 1) / NT, Bn);
    cost_kernel<<<cgrid, NT>>>(pc, pb, lab, tb);
    hungarian_kernel<<<Bn, NTH>>>();
    loss_kernel<<<Bn, NT>>>(pc, pb, lab, tb, out);
}

// round 5
// speedup vs baseline: 9.7312x; 2.0298x over previous
#include <cuda_runtime.h>
#include <cuda_bf16.h>
#include <float.h>
#include <math.h>

#define NUM_CLASSES 13
#define C1 (NUM_CLASSES + 1)   // 14
#define Bn 64
#define Qn 900
#define Tn 128
#define NT 256
#define NTH 256                // hungarian threads (8 warps)
#define NWARP (NTH / 32)
#define JPT 4                  // columns per thread (float4)
#define NACT (Qn / JPT)        // 225 active scan threads

// ---- scratch (static device globals; no allocation allowed) ----
__device__ __align__(256) float g_cost[Bn * Tn * Qn];   // cost[b][t][q]
__device__ float  g_lse[Bn * Qn];         // logsumexp per (b,q)
__device__ int    g_pred[Bn * Tn];        // query index assigned to target t
__device__ double g_partial[Bn];          // per-image loss
__device__ int    g_ctr = 0;              // completion counter (reset each run)

// order-preserving float <-> uint32 (no NaNs in costs)
__device__ __forceinline__ unsigned enc_f(float f) {
    unsigned u = __float_as_uint(f);
    return (u & 0x80000000u) ? ~u : (u | 0x80000000u);
}
__device__ __forceinline__ float dec_f(unsigned e) {
    unsigned x = (e & 0x80000000u) ? (e & 0x7fffffffu) : ~e;
    return __uint_as_float(x);
}

// ============================================================================
// 1) Cost matrix: C[b][t][q] = -softmax(pc[b,q])[label[b,t]] + L1(pb[b,q], tb[b,t])
// ============================================================================
__global__ __launch_bounds__(NT) void cost_kernel(
    const float* __restrict__ pc,   // [B,Q,14]
    const float* __restrict__ pb,   // [B,Q,4]
    const int*   __restrict__ lab,  // [B,T]
    const float* __restrict__ tb)   // [B,T,4]
{
    int b = blockIdx.y;
    int q = blockIdx.x * blockDim.x + threadIdx.x;

    __shared__ float s_tb[Tn * 4];
    __shared__ int   s_lab[Tn];
    for (int i = threadIdx.x; i < Tn * 4; i += NT) s_tb[i] = tb[b * Tn * 4 + i];
    for (int i = threadIdx.x; i < Tn; i += NT)     s_lab[i] = lab[b * Tn + i];
    __syncthreads();
    if (q >= Qn) return;

    const float* lg = pc + (size_t)(b * Qn + q) * C1;
    float m = lg[0];
    #pragma unroll
    for (int c = 1; c < C1; c++) m = fmaxf(m, lg[c]);
    float e[C1]; float se = 0.f;
    #pragma unroll
    for (int c = 0; c < C1; c++) { e[c] = __expf(lg[c] - m); se += e[c]; }
    float inv = 1.0f / se;
    g_lse[b * Qn + q] = m + logf(se);

    const float4 pbq = *reinterpret_cast<const float4*>(pb + (size_t)(b * Qn + q) * 4);

    float* crow = g_cost + (size_t)b * Tn * Qn + q;
    #pragma unroll 4
    for (int t = 0; t < Tn; t++) {
        float cb = fabsf(pbq.x - s_tb[t * 4 + 0]) + fabsf(pbq.y - s_tb[t * 4 + 1])
                 + fabsf(pbq.z - s_tb[t * 4 + 2]) + fabsf(pbq.w - s_tb[t * 4 + 3]);
        float cc = -e[s_lab[t]] * inv;
        crow[(size_t)t * Qn] = cb + cc;
    }
}

// ============================================================================
// 2) Hungarian (JV) with greedy row-min initialization + deferred duals.
//    One CTA (256 threads) per image; rows = 128 targets, cols = 900 queries.
//    Init: u[i] = min_j cost[i][j] (tight, exact in float), greedy-assign
//    argmin columns; only collided rows (~10) need augmenting phases.
// ============================================================================
__global__ __launch_bounds__(NTH) void hungarian_kernel()
{
    int b = blockIdx.x;
    int tid = threadIdx.x;
    int lane = tid & 31, warp = tid >> 5;

    __shared__ float u[Tn + 1];
    __shared__ float v[Qn + 1];
    __shared__ float minv[Qn + 1];   // minv_abs = minv_true + C
    __shared__ float tu[Qn + 1];     // C at the moment column became used
    __shared__ int   way[Qn + 1];
    __shared__ int   p[Qn + 1];
    __shared__ int   rowarg[Tn + 1];
    __shared__ unsigned char used[Qn + 1];
    __shared__ unsigned char s_assigned[Tn + 1];
    __shared__ unsigned s_wv[2][NWARP];   // parity-double-buffered warp minima
    __shared__ int      s_wi[2][NWARP];

    for (int j = tid; j <= Qn; j += NTH) { v[j] = 0.f; p[j] = 0; minv[j] = FLT_MAX; used[j] = 0; }
    __syncthreads();

    const float* cost = g_cost + (size_t)b * Tn * Qn;

    // ---- row minima: one row per warp, packed (enc(value) << 32 | j) ----
    for (int i = warp + 1; i <= Tn; i += NWARP) {
        const float* crow = cost + (size_t)(i - 1) * Qn;
        float4 c4[8];
        #pragma unroll
        for (int s = 0; s < 7; s++)
            c4[s] = __ldg(reinterpret_cast<const float4*>(crow + s * 128 + lane * 4));
        c4[7] = (lane == 0) ? __ldg(reinterpret_cast<const float4*>(crow + 896))
                            : make_float4(FLT_MAX, FLT_MAX, FLT_MAX, FLT_MAX);
        unsigned long long best = ~0ull;
        #pragma unroll
        for (int s = 0; s < 8; s++) {
            int j0 = (s < 7) ? (s * 128 + lane * 4) : 896;
            #pragma unroll
            for (int k = 0; k < 4; k++) {
                unsigned long long e =
                    ((unsigned long long)enc_f((&c4[s].x)[k]) << 32) | (unsigned)(j0 + k + 1);
                if (e < best) best = e;
            }
        }
        #pragma unroll
        for (int s = 16; s; s >>= 1) {
            unsigned long long o = __shfl_down_sync(0xffffffffu, best, s);
            if (o < best) best = o;
        }
        if (lane == 0) {
            u[i] = dec_f((unsigned)(best >> 32));   // exact matrix entry -> tight edge
            rowarg[i] = (int)(best & 0xffffffffu);
        }
    }
    __syncthreads();

    // ---- greedy assignment (serial, trivial) ----
    if (tid == 0) {
        for (int i = 1; i <= Tn; i++) {
            int j = rowarg[i];
            if (p[j] == 0) { p[j] = i; s_assigned[i] = 1; }
            else s_assigned[i] = 0;
        }
    }
    __syncthreads();

    const bool valid = (tid < NACT);
    const int  jbase = JPT * tid + 1;     // first owned column (1-based)

    for (int i = 1; i <= Tn; i++) {
        if (s_assigned[i]) continue;
        if (tid == 0) { p[0] = i; used[0] = 1; tu[0] = 0.f; }
        __syncthreads();

        int   i0 = i;
        float C  = 0.f;
        int   lastj1 = 0;
        float Cmark = 0.f;
        int   it = 0;
        int   jfinal; float Cf;

        while (true) {
            int par = it & 1;
            // one L2 round trip for this thread's 4 columns of the scanned row
            float4 cr = make_float4(0.f, 0.f, 0.f, 0.f);
            if (valid) cr = __ldg(reinterpret_cast<const float4*>(
                                  cost + (size_t)(i0 - 1) * Qn + (jbase - 1)));
            float aC = u[i0] - C;
            // deferred mark of previous j1 (race-free: scans exclude j==lastj1)
            if (tid == 0 && it > 0) { used[lastj1] = 1; tu[lastj1] = Cmark; }

            unsigned benc = 0xFFFFFFFFu; int bj = 0x7FFFFFFF;
            if (valid) {
                #pragma unroll
                for (int k = 0; k < JPT; k++) {
                    int j = jbase + k;
                    float cv = (&cr.x)[k];
                    if (!used[j] && j != lastj1) {
                        float r = cv - aC - v[j];
                        float mv = minv[j];
                        if (r < mv) { mv = r; minv[j] = r; way[j] = lastj1; }
                        unsigned e = enc_f(mv);
                        if (e < benc) { benc = e; bj = j; }   // ascending j => first kept
                    }
                }
            }
            // warp argmin via two REDUX ops (exact lexicographic (value, j))
            unsigned m = __reduce_min_sync(0xffffffffu, benc);
            int cand = (benc == m) ? bj : 0x7FFFFFFF;
            int jm = __reduce_min_sync(0xffffffffu, cand);
            if (lane == 0) { s_wv[par][warp] = m; s_wi[par][warp] = jm; }
            __syncthreads();

            // every thread reduces the 8 leader slots (no second barrier)
            unsigned ge = s_wv[par][0]; int gj = s_wi[par][0];
            #pragma unroll
            for (int w = 1; w < NWARP; w++) {
                unsigned e2 = s_wv[par][w]; int j2 = s_wi[par][w];
                if (e2 < ge || (e2 == ge && j2 < gj)) { ge = e2; gj = j2; }
            }
            float Cn = dec_f(ge);
            int j1 = gj;
            int i0n = p[j1];
            if (i0n == 0) { jfinal = j1; Cf = Cn; break; }
            Cmark = Cn; lastj1 = j1; C = Cn; i0 = i0n; it++;
        }

        // apply duals (p BEFORE augmentation) + reset state for next phase
        for (int j = tid; j <= Qn; j += NTH) {
            if (used[j]) {
                float dv = Cf - tu[j];
                v[j] -= dv;              // v[0] dummy, never read
                u[p[j]] += dv;           // includes u[i] via p[0]=i
                used[j] = 0;
            }
            minv[j] = FLT_MAX;
        }
        __syncthreads();
        if (tid == 0) {                  // augment along alternating path
            int j0 = jfinal;
            while (j0) { int jp = way[j0]; p[j0] = p[jp]; j0 = jp; }
        }
        __syncthreads();
    }

    for (int j = tid + 1; j <= Qn; j += NTH) {
        int pi = p[j];
        if (pi > 0) g_pred[b * Tn + pi - 1] = j - 1;
    }
}

// ============================================================================
// 3) Per-image loss + last-block global reduction (fused finalize)
// ============================================================================
__global__ __launch_bounds__(NT) void loss_kernel(
    const float* __restrict__ pc,
    const float* __restrict__ pb,
    const int*   __restrict__ lab,
    const float* __restrict__ tb,
    float* __restrict__ out)
{
    int b = blockIdx.x;
    int tid = threadIdx.x;
    __shared__ int tcl[Qn];
    __shared__ double sred[NT];
    __shared__ int s_last;

    double l1 = 0.0, gsum = 0.0;
    if (tid < Tn) {
        int t = tid;
        int qi = g_pred[b * Tn + t];
        const float4 P = *reinterpret_cast<const float4*>(pb + (size_t)(b * Qn + qi) * 4);
        const float4 G = *reinterpret_cast<const float4*>(tb + (size_t)(b * Tn + t) * 4);
        double px = P.x, py = P.y, pw = P.z, ph = P.w;
        double gx = G.x, gy = G.y, gw = G.z, gh = G.w;
        l1 = fabs(px - gx) + fabs(py - gy) + fabs(pw - gw) + fabs(ph - gh);

        double p0 = px - 0.5 * pw, p1 = py - 0.5 * ph, p2 = px + 0.5 * pw, p3 = py + 0.5 * ph;
        double g0 = gx - 0.5 * gw, g1 = gy - 0.5 * gh, g2 = gx + 0.5 * gw, g3 = gy + 0.5 * gh;
        double a1 = (p2 - p0) * (p3 - p1);
        double a2 = (g2 - g0) * (g3 - g1);
        double iw = fmin(p2, g2) - fmax(p0, g0); iw = iw > 0.0 ? iw : 0.0;
        double ih = fmin(p3, g3) - fmax(p1, g1); ih = ih > 0.0 ? ih : 0.0;
        double inter = iw * ih;
        double uni = a1 + a2 - inter;
        double iou = inter / uni;
        double cw = fmax(p2, g2) - fmin(p0, g0);
        double ch = fmax(p3, g3) - fmin(p1, g1);
        double ac = cw * ch;
        double giou = iou - (ac - uni) / ac;
        gsum = 1.0 - giou;
    }

    for (int q = tid; q < Qn; q += NT) tcl[q] = NUM_CLASSES;
    __syncthreads();
    if (tid < Tn) tcl[g_pred[b * Tn + tid]] = lab[b * Tn + tid];
    __syncthreads();

    double wn = 0.0, ws = 0.0;
    for (int q = tid; q < Qn; q += NT) {
        int c = tcl[q];
        double w = (c == NUM_CLASSES) ? 0.05 : 1.0;
        double nll = (double)g_lse[b * Qn + q] - (double)pc[(size_t)(b * Qn + q) * C1 + c];
        wn += w * nll; ws += w;
    }

    sred[tid] = l1;   __syncthreads();
    for (int s = NT / 2; s; s >>= 1) { if (tid < s) sred[tid] += sred[tid + s]; __syncthreads(); }
    double l1t = sred[0]; __syncthreads();
    sred[tid] = gsum; __syncthreads();
    for (int s = NT / 2; s; s >>= 1) { if (tid < s) sred[tid] += sred[tid + s]; __syncthreads(); }
    double gst = sred[0]; __syncthreads();
    sred[tid] = wn;   __syncthreads();
    for (int s = NT / 2; s; s >>= 1) { if (tid < s) sred[tid] += sred[tid + s]; __syncthreads(); }
    double wnt = sred[0]; __syncthreads();
    sred[tid] = ws;   __syncthreads();
    for (int s = NT / 2; s; s >>= 1) { if (tid < s) sred[tid] += sred[tid + s]; __syncthreads(); }
    double wst = sred[0]; __syncthreads();

    if (tid == 0) {
        double bbox = 5.0 * (l1t / (Tn * 4.0)) + 2.0 * (gst / Tn);
        g_partial[b] = bbox + wnt / wst;
        __threadfence();
        int t = atomicAdd(&g_ctr, 1);
        s_last = (t == Bn - 1);
    }
    __syncthreads();

    if (s_last) {
        double val = (tid < Bn) ? ((volatile double*)g_partial)[tid] : 0.0;
        sred[tid] = val; __syncthreads();
        for (int s = NT / 2; s; s >>= 1) { if (tid < s) sred[tid] += sred[tid + s]; __syncthreads(); }
        if (tid == 0) {
            out[0] = (float)(sred[0] / (double)(Bn * Tn));
            g_ctr = 0;                      // restore for next graph replay
        }
    }
}

extern "C" void kernel_launch(void* const* d_in, const int* in_sizes, int n_in,
                              void* d_out, int out_size)
{
    const float* pc  = (const float*)d_in[0];   // predicted_class [64,900,14]
    const float* pb  = (const float*)d_in[1];   // predicted_bbox  [64,900,4]
    const int*   lab = (const int*)  d_in[2];   // target_labels   [64,128]
    const float* tb  = (const float*)d_in[3];   // target_boxes    [64,128,4]
    float* out = (float*)d_out;

    dim3 cgrid((Qn + NT - 1) / NT, Bn);
    cost_kernel<<<cgrid, NT>>>(pc, pb, lab, tb);
    hungarian_kernel<<<Bn, NTH>>>();
    loss_kernel<<<Bn, NT>>>(pc, pb, lab, tb, out);
}

// round 6
// speedup vs baseline: 10.2589x; 1.0542x over previous
#include <cuda_runtime.h>
#include <cuda_bf16.h>
#include <float.h>
#include <math.h>

#define NUM_CLASSES 13
#define C1 (NUM_CLASSES + 1)   // 14
#define Bn 64
#define Qn 900
#define Tn 128
#define NT 256
#define NTH 256                // hungarian threads (8 warps)
#define NWARP (NTH / 32)
#define JPT 4                  // columns per thread (float4)
#define NACT (Qn / JPT)        // 225 active scan threads
#define TSPLIT 2
#define TCH (Tn / TSPLIT)      // 64 targets per cost CTA

// ---- scratch (static device globals; no allocation allowed) ----
__device__ __align__(256) float g_cost[Bn * Tn * Qn];   // cost[b][t][q]
__device__ float  g_lse[Bn * Qn];         // logsumexp per (b,q)
__device__ int    g_pred[Bn * Tn];        // query index assigned to target t
__device__ double g_partial[Bn];          // per-image loss
__device__ int    g_ctr = 0;              // completion counter (reset each run)

// order-preserving float <-> uint32 (no NaNs in costs)
__device__ __forceinline__ unsigned enc_f(float f) {
    unsigned u = __float_as_uint(f);
    return (u & 0x80000000u) ? ~u : (u | 0x80000000u);
}
__device__ __forceinline__ float dec_f(unsigned e) {
    unsigned x = (e & 0x80000000u) ? (e & 0x7fffffffu) : ~e;
    return __uint_as_float(x);
}

// ============================================================================
// 1) Cost matrix. Shared -prob table kills the dynamic register-index chain;
//    gridDim.z splits the target loop for 2x parallelism.
// ============================================================================
__global__ __launch_bounds__(NT) void cost_kernel(
    const float* __restrict__ pc,   // [B,Q,14]
    const float* __restrict__ pb,   // [B,Q,4]
    const int*   __restrict__ lab,  // [B,T]
    const float* __restrict__ tb)   // [B,T,4]
{
    int b    = blockIdx.y;
    int tseg = blockIdx.z;
    int t0   = tseg * TCH;
    int tid  = threadIdx.x;
    int q    = blockIdx.x * NT + tid;

    __shared__ float4 s_tb4[TCH];
    __shared__ int    s_lab[TCH];
    __shared__ float  s_negp[C1][NT];   // -prob[c] per thread (class-major: conflict-free)

    for (int i = tid; i < TCH; i += NT) {
        s_tb4[i] = reinterpret_cast<const float4*>(tb)[b * Tn + t0 + i];
        s_lab[i] = lab[b * Tn + t0 + i];
    }

    float4 pbq = make_float4(0.f, 0.f, 0.f, 0.f);
    if (q < Qn) {
        const float* lg = pc + (size_t)(b * Qn + q) * C1;
        float m = lg[0];
        #pragma unroll
        for (int c = 1; c < C1; c++) m = fmaxf(m, lg[c]);
        float e[C1]; float se = 0.f;
        #pragma unroll
        for (int c = 0; c < C1; c++) { e[c] = __expf(lg[c] - m); se += e[c]; }
        float inv = 1.0f / se;
        #pragma unroll
        for (int c = 0; c < C1; c++) s_negp[c][tid] = -e[c] * inv;
        if (tseg == 0) g_lse[b * Qn + q] = m + logf(se);
        pbq = *reinterpret_cast<const float4*>(pb + (size_t)(b * Qn + q) * 4);
    }
    __syncthreads();
    if (q >= Qn) return;

    float* crow = g_cost + (size_t)b * Tn * Qn + (size_t)t0 * Qn + q;
    #pragma unroll 8
    for (int t = 0; t < TCH; t++) {
        float4 tb4 = s_tb4[t];
        float cc = s_negp[s_lab[t]][tid];
        float cb = fabsf(pbq.x - tb4.x) + fabsf(pbq.y - tb4.y)
                 + fabsf(pbq.z - tb4.z) + fabsf(pbq.w - tb4.w);
        crow[(size_t)t * Qn] = cb + cc;
    }
}

// ============================================================================
// 2) Hungarian (JV): row-min greedy init + Augmenting Row Reduction (ARR)
//    + Dijkstra phases (deferred duals) for any stragglers.
//    One CTA (256 threads) per image. Thread t owns columns 4t+1..4t+4.
// ============================================================================
__global__ __launch_bounds__(NTH) void hungarian_kernel()
{
    int b = blockIdx.x;
    int tid = threadIdx.x;
    int lane = tid & 31, warp = tid >> 5;

    __shared__ float u[Tn + 1];
    __shared__ float v[Qn + 1];
    __shared__ float minv[Qn + 1];   // minv_abs = minv_true + C
    __shared__ float tu[Qn + 1];     // C at the moment column became used
    __shared__ int   way[Qn + 1];
    __shared__ int   p[Qn + 1];
    __shared__ int   rowarg[Tn + 1];
    __shared__ int   s_queue[Tn + 1];
    __shared__ unsigned char used[Qn + 1];
    __shared__ unsigned char s_assigned[Tn + 1];
    __shared__ unsigned s_wv[2][NWARP];   // parity-double-buffered warp minima
    __shared__ int      s_wi[2][NWARP];
    __shared__ unsigned long long s_a1[NWARP];   // ARR warp (min1,j) packed
    __shared__ unsigned             s_a2[NWARP]; // ARR warp min2 value
    __shared__ int s_cur, s_nfree;

    for (int j = tid; j <= Qn; j += NTH) { v[j] = 0.f; p[j] = 0; minv[j] = FLT_MAX; used[j] = 0; }
    __syncthreads();

    const float* cost = g_cost + (size_t)b * Tn * Qn;

    // ---- row minima: one row per warp, packed (enc(value) << 32 | j) ----
    for (int i = warp + 1; i <= Tn; i += NWARP) {
        const float* crow = cost + (size_t)(i - 1) * Qn;
        float4 c4[8];
        #pragma unroll
        for (int s = 0; s < 7; s++)
            c4[s] = __ldg(reinterpret_cast<const float4*>(crow + s * 128 + lane * 4));
        c4[7] = (lane == 0) ? __ldg(reinterpret_cast<const float4*>(crow + 896))
                            : make_float4(FLT_MAX, FLT_MAX, FLT_MAX, FLT_MAX);
        unsigned long long best = ~0ull;
        #pragma unroll
        for (int s = 0; s < 8; s++) {
            int j0 = (s < 7) ? (s * 128 + lane * 4) : 896;
            #pragma unroll
            for (int k = 0; k < 4; k++) {
                unsigned long long e =
                    ((unsigned long long)enc_f((&c4[s].x)[k]) << 32) | (unsigned)(j0 + k + 1);
                if (e < best) best = e;
            }
        }
        #pragma unroll
        for (int s = 16; s; s >>= 1) {
            unsigned long long o = __shfl_down_sync(0xffffffffu, best, s);
            if (o < best) best = o;
        }
        if (lane == 0) {
            u[i] = dec_f((unsigned)(best >> 32));   // exact matrix entry -> tight edge
            rowarg[i] = (int)(best & 0xffffffffu);
        }
    }
    __syncthreads();

    // ---- greedy assignment + free queue (serial, trivial) ----
    if (tid == 0) {
        for (int i = 1; i <= Tn; i++) {
            int j = rowarg[i];
            if (p[j] == 0) { p[j] = i; s_assigned[i] = 1; }
            else s_assigned[i] = 0;
        }
        int nf = 0;
        for (int i = 1; i <= Tn; i++) if (!s_assigned[i]) s_queue[nf++] = i;
        s_nfree = nf;
        s_cur = nf ? s_queue[0] : 0;
    }
    __syncthreads();

    const bool valid = (tid < NACT);
    const int  jbase = JPT * tid + 1;     // first owned column (1-based)

    // ---- ARR: each event scans one row, takes argmin column (maybe stealing),
    //      u[i]=min2, v[j1]-=(min2-min1). Tight+feasible at every step. ----
    {
        int qhead = 1;        // only thread 0 uses
        int cap = 8 * Tn;     // safety: leftovers go to Dijkstra
        while (true) {
            int i = s_cur;
            if (i == 0) break;

            unsigned long long m1 = ~0ull; unsigned m2v = 0xFFFFFFFFu;
            if (valid) {
                float4 cr = __ldg(reinterpret_cast<const float4*>(
                                  cost + (size_t)(i - 1) * Qn + (jbase - 1)));
                #pragma unroll
                for (int k = 0; k < JPT; k++) {
                    int j = jbase + k;
                    float r = (&cr.x)[k] - v[j];
                    unsigned long long pk =
                        ((unsigned long long)enc_f(r) << 32) | (unsigned)j;
                    if (pk < m1) { m2v = min(m2v, (unsigned)(m1 >> 32)); m1 = pk; }
                    else { unsigned ev = (unsigned)(pk >> 32); if (ev < m2v) m2v = ev; }
                }
            }
            #pragma unroll
            for (int s = 16; s; s >>= 1) {
                unsigned long long o1 = __shfl_down_sync(0xffffffffu, m1, s);
                unsigned            o2 = __shfl_down_sync(0xffffffffu, m2v, s);
                if (o1 < m1) {
                    unsigned a1v = (unsigned)(m1 >> 32);
                    m1 = o1;
                    m2v = min(min(m2v, o2), a1v);
                } else {
                    unsigned b1v = (unsigned)(o1 >> 32);
                    m2v = min(m2v, min(o2, b1v));
                }
            }
            if (lane == 0) { s_a1[warp] = m1; s_a2[warp] = m2v; }
            __syncthreads();

            unsigned long long g1 = s_a1[0]; unsigned g2 = s_a2[0];
            #pragma unroll
            for (int w = 1; w < NWARP; w++) {
                unsigned long long o1 = s_a1[w]; unsigned o2 = s_a2[w];
                if (o1 < g1) { g2 = min(min(g2, o2), (unsigned)(g1 >> 32)); g1 = o1; }
                else         { g2 = min(g2, min(o2, (unsigned)(o1 >> 32))); }
            }
            int   j1   = (int)(g1 & 0xffffffffu);
            float min1 = dec_f((unsigned)(g1 >> 32));
            float min2 = dec_f(g2);

            if (tid == ((j1 - 1) >> 2)) v[j1] -= (min2 - min1);  // column owner
            if (tid == 0) {
                u[i] = min2;
                int k = p[j1];
                p[j1] = i; s_assigned[i] = 1;
                if (--cap <= 0) s_cur = 0;
                else if (k) { s_assigned[k] = 0; s_cur = k; }
                else s_cur = (qhead < s_nfree) ? s_queue[qhead++] : 0;
            }
            __syncthreads();
        }
    }

    // ---- Dijkstra phases for any remaining free rows ----
    for (int i = 1; i <= Tn; i++) {
        if (s_assigned[i]) continue;
        if (tid == 0) { p[0] = i; used[0] = 1; tu[0] = 0.f; }
        __syncthreads();

        int   i0 = i;
        float C  = 0.f;
        int   lastj1 = 0;
        float Cmark = 0.f;
        int   it = 0;
        int   jfinal; float Cf;

        while (true) {
            int par = it & 1;
            float4 cr = make_float4(0.f, 0.f, 0.f, 0.f);
            if (valid) cr = __ldg(reinterpret_cast<const float4*>(
                                  cost + (size_t)(i0 - 1) * Qn + (jbase - 1)));
            float aC = u[i0] - C;
            if (tid == 0 && it > 0) { used[lastj1] = 1; tu[lastj1] = Cmark; }

            unsigned benc = 0xFFFFFFFFu; int bj = 0x7FFFFFFF;
            if (valid) {
                #pragma unroll
                for (int k = 0; k < JPT; k++) {
                    int j = jbase + k;
                    float cv = (&cr.x)[k];
                    if (!used[j] && j != lastj1) {
                        float r = cv - aC - v[j];
                        float mv = minv[j];
                        if (r < mv) { mv = r; minv[j] = r; way[j] = lastj1; }
                        unsigned e = enc_f(mv);
                        if (e < benc) { benc = e; bj = j; }
                    }
                }
            }
            unsigned m = __reduce_min_sync(0xffffffffu, benc);
            int cand = (benc == m) ? bj : 0x7FFFFFFF;
            int jm = __reduce_min_sync(0xffffffffu, cand);
            if (lane == 0) { s_wv[par][warp] = m; s_wi[par][warp] = jm; }
            __syncthreads();

            unsigned ge = s_wv[par][0]; int gj = s_wi[par][0];
            #pragma unroll
            for (int w = 1; w < NWARP; w++) {
                unsigned e2 = s_wv[par][w]; int j2 = s_wi[par][w];
                if (e2 < ge || (e2 == ge && j2 < gj)) { ge = e2; gj = j2; }
            }
            float Cn = dec_f(ge);
            int j1 = gj;
            int i0n = p[j1];
            if (i0n == 0) { jfinal = j1; Cf = Cn; break; }
            Cmark = Cn; lastj1 = j1; C = Cn; i0 = i0n; it++;
        }

        for (int j = tid; j <= Qn; j += NTH) {
            if (used[j]) {
                float dv = Cf - tu[j];
                v[j] -= dv;
                u[p[j]] += dv;
                used[j] = 0;
            }
            minv[j] = FLT_MAX;
        }
        __syncthreads();
        if (tid == 0) {
            int j0 = jfinal;
            while (j0) { int jp = way[j0]; p[j0] = p[jp]; j0 = jp; }
            s_assigned[i] = 1;
        }
        __syncthreads();
    }

    for (int j = tid + 1; j <= Qn; j += NTH) {
        int pi = p[j];
        if (pi > 0) g_pred[b * Tn + pi - 1] = j - 1;
    }
}

// ============================================================================
// 3) Per-image loss + last-block global reduction (fused finalize)
// ============================================================================
__global__ __launch_bounds__(NT) void loss_kernel(
    const float* __restrict__ pc,
    const float* __restrict__ pb,
    const int*   __restrict__ lab,
    const float* __restrict__ tb,
    float* __restrict__ out)
{
    int b = blockIdx.x;
    int tid = threadIdx.x;
    __shared__ int tcl[Qn];
    __shared__ double sred[NT];
    __shared__ int s_last;

    double l1 = 0.0, gsum = 0.0;
    if (tid < Tn) {
        int t = tid;
        int qi = g_pred[b * Tn + t];
        const float4 P = *reinterpret_cast<const float4*>(pb + (size_t)(b * Qn + qi) * 4);
        const float4 G = *reinterpret_cast<const float4*>(tb + (size_t)(b * Tn + t) * 4);
        double px = P.x, py = P.y, pw = P.z, ph = P.w;
        double gx = G.x, gy = G.y, gw = G.z, gh = G.w;
        l1 = fabs(px - gx) + fabs(py - gy) + fabs(pw - gw) + fabs(ph - gh);

        double p0 = px - 0.5 * pw, p1 = py - 0.5 * ph, p2 = px + 0.5 * pw, p3 = py + 0.5 * ph;
        double g0 = gx - 0.5 * gw, g1 = gy - 0.5 * gh, g2 = gx + 0.5 * gw, g3 = gy + 0.5 * gh;
        double a1 = (p2 - p0) * (p3 - p1);
        double a2 = (g2 - g0) * (g3 - g1);
        double iw = fmin(p2, g2) - fmax(p0, g0); iw = iw > 0.0 ? iw : 0.0;
        double ih = fmin(p3, g3) - fmax(p1, g1); ih = ih > 0.0 ? ih : 0.0;
        double inter = iw * ih;
        double uni = a1 + a2 - inter;
        double iou = inter / uni;
        double cw = fmax(p2, g2) - fmin(p0, g0);
        double ch = fmax(p3, g3) - fmin(p1, g1);
        double ac = cw * ch;
        double giou = iou - (ac - uni) / ac;
        gsum = 1.0 - giou;
    }

    for (int q = tid; q < Qn; q += NT) tcl[q] = NUM_CLASSES;
    __syncthreads();
    if (tid < Tn) tcl[g_pred[b * Tn + tid]] = lab[b * Tn + tid];
    __syncthreads();

    double wn = 0.0, ws = 0.0;
    for (int q = tid; q < Qn; q += NT) {
        int c = tcl[q];
        double w = (c == NUM_CLASSES) ? 0.05 : 1.0;
        double nll = (double)g_lse[b * Qn + q] - (double)pc[(size_t)(b * Qn + q) * C1 + c];
        wn += w * nll; ws += w;
    }

    sred[tid] = l1;   __syncthreads();
    for (int s = NT / 2; s; s >>= 1) { if (tid < s) sred[tid] += sred[tid + s]; __syncthreads(); }
    double l1t = sred[0]; __syncthreads();
    sred[tid] = gsum; __syncthreads();
    for (int s = NT / 2; s; s >>= 1) { if (tid < s) sred[tid] += sred[tid + s]; __syncthreads(); }
    double gst = sred[0]; __syncthreads();
    sred[tid] = wn;   __syncthreads();
    for (int s = NT / 2; s; s >>= 1) { if (tid < s) sred[tid] += sred[tid + s]; __syncthreads(); }
    double wnt = sred[0]; __syncthreads();
    sred[tid] = ws;   __syncthreads();
    for (int s = NT / 2; s; s >>= 1) { if (tid < s) sred[tid] += sred[tid + s]; __syncthreads(); }
    double wst = sred[0]; __syncthreads();

    if (tid == 0) {
        double bbox = 5.0 * (l1t / (Tn * 4.0)) + 2.0 * (gst / Tn);
        g_partial[b] = bbox + wnt / wst;
        __threadfence();
        int t = atomicAdd(&g_ctr, 1);
        s_last = (t == Bn - 1);
    }
    __syncthreads();

    if (s_last) {
        double val = (tid < Bn) ? ((volatile double*)g_partial)[tid] : 0.0;
        sred[tid] = val; __syncthreads();
        for (int s = NT / 2; s; s >>= 1) { if (tid < s) sred[tid] += sred[tid + s]; __syncthreads(); }
        if (tid == 0) {
            out[0] = (float)(sred[0] / (double)(Bn * Tn));
            g_ctr = 0;                      // restore for next graph replay
        }
    }
}

extern "C" void kernel_launch(void* const* d_in, const int* in_sizes, int n_in,
                              void* d_out, int out_size)
{
    const float* pc  = (const float*)d_in[0];   // predicted_class [64,900,14]
    const float* pb  = (const float*)d_in[1];   // predicted_bbox  [64,900,4]
    const int*   lab = (const int*)  d_in[2];   // target_labels   [64,128]
    const float* tb  = (const float*)d_in[3];   // target_boxes    [64,128,4]
    float* out = (float*)d_out;

    dim3 cgrid((Qn + NT - 1) / NT, Bn, TSPLIT);
    cost_kernel<<<cgrid, NT>>>(pc, pb, lab, tb);
    hungarian_kernel<<<Bn, NTH>>>();
    loss_kernel<<<Bn, NT>>>(pc, pb, lab, tb, out);
}

// round 7
// speedup vs baseline: 12.0654x; 1.1761x over previous
#include <cuda_runtime.h>
#include <cuda_bf16.h>
#include <float.h>
#include <math.h>

#define NUM_CLASSES 13
#define C1 (NUM_CLASSES + 1)   // 14
#define Bn 64
#define Qn 900
#define Tn 128
#define NT 256
#define NTH 256                // hungarian threads (8 warps)
#define NWARP (NTH / 32)
#define JPT 4                  // columns per thread (float4)
#define NACT (Qn / JPT)        // 225 active scan threads
#define TSPLIT 2
#define TCH (Tn / TSPLIT)      // 64 targets per cost CTA

// ---- scratch (static device globals; no allocation allowed) ----
__device__ __align__(256) float g_cost[Bn * Tn * Qn];   // cost[b][t][q]
__device__ float  g_lse[Bn * Qn];         // logsumexp per (b,q)
__device__ double g_partial[Bn];          // per-image loss
__device__ int    g_ctr = 0;              // completion counter (reset each run)

// order-preserving float <-> uint32 (no NaNs in costs)
__device__ __forceinline__ unsigned enc_f(float f) {
    unsigned u = __float_as_uint(f);
    return (u & 0x80000000u) ? ~u : (u | 0x80000000u);
}
__device__ __forceinline__ float dec_f(unsigned e) {
    unsigned x = (e & 0x80000000u) ? (e & 0x7fffffffu) : ~e;
    return __uint_as_float(x);
}

// ============================================================================
// 1) Cost matrix (proven R6 version): shared -prob table, z-split over targets
// ============================================================================
__global__ __launch_bounds__(NT) void cost_kernel(
    const float* __restrict__ pc,   // [B,Q,14]
    const float* __restrict__ pb,   // [B,Q,4]
    const int*   __restrict__ lab,  // [B,T]
    const float* __restrict__ tb)   // [B,T,4]
{
    int b    = blockIdx.y;
    int tseg = blockIdx.z;
    int t0   = tseg * TCH;
    int tid  = threadIdx.x;
    int q    = blockIdx.x * NT + tid;

    __shared__ float4 s_tb4[TCH];
    __shared__ int    s_lab[TCH];
    __shared__ float  s_negp[C1][NT];

    for (int i = tid; i < TCH; i += NT) {
        s_tb4[i] = reinterpret_cast<const float4*>(tb)[b * Tn + t0 + i];
        s_lab[i] = lab[b * Tn + t0 + i];
    }

    float4 pbq = make_float4(0.f, 0.f, 0.f, 0.f);
    if (q < Qn) {
        const float* lg = pc + (size_t)(b * Qn + q) * C1;
        float m = lg[0];
        #pragma unroll
        for (int c = 1; c < C1; c++) m = fmaxf(m, lg[c]);
        float e[C1]; float se = 0.f;
        #pragma unroll
        for (int c = 0; c < C1; c++) { e[c] = __expf(lg[c] - m); se += e[c]; }
        float inv = 1.0f / se;
        #pragma unroll
        for (int c = 0; c < C1; c++) s_negp[c][tid] = -e[c] * inv;
        if (tseg == 0) g_lse[b * Qn + q] = m + logf(se);
        pbq = *reinterpret_cast<const float4*>(pb + (size_t)(b * Qn + q) * 4);
    }
    __syncthreads();
    if (q >= Qn) return;

    float* crow = g_cost + (size_t)b * Tn * Qn + (size_t)t0 * Qn + q;
    #pragma unroll 8
    for (int t = 0; t < TCH; t++) {
        float4 tb4 = s_tb4[t];
        float cc = s_negp[s_lab[t]][tid];
        float cb = fabsf(pbq.x - tb4.x) + fabsf(pbq.y - tb4.y)
                 + fabsf(pbq.z - tb4.z) + fabsf(pbq.w - tb4.w);
        crow[(size_t)t * Qn] = cb + cc;
    }
}

// ============================================================================
// 2) Hungarian (JV: greedy row-min init + Dijkstra phases, deferred duals)
//    with per-column state (v, minv, tu, used) in the OWNER THREAD's
//    registers, fused with the per-image loss + global finalize.
//    One CTA (256 threads) per image; thread t owns columns 4t+1..4t+4.
// ============================================================================
__global__ __launch_bounds__(NTH) void hungarian_loss_kernel(
    const float* __restrict__ pc,
    const float* __restrict__ pb,
    const int*   __restrict__ lab,
    const float* __restrict__ tb,
    float* __restrict__ out)
{
    int b = blockIdx.x;
    int tid = threadIdx.x;
    int lane = tid & 31, warp = tid >> 5;

    __shared__ float u[Tn + 1];
    __shared__ int   way[Qn + 1];
    __shared__ int   p[Qn + 1];
    __shared__ int   rowq[Tn + 1];       // rowarg, later qi-per-target
    __shared__ unsigned char s_assigned[Tn + 1];
    __shared__ unsigned s_wv[2][NWARP];
    __shared__ int      s_wi[2][NWARP];
    __shared__ double   sred[NTH];
    __shared__ int      s_last;

    for (int j = tid; j <= Qn; j += NTH) p[j] = 0;
    __syncthreads();

    const float* cost = g_cost + (size_t)b * Tn * Qn;
    const bool valid = (tid < NACT);
    const int  jbase = JPT * tid + 1;     // first owned column (1-based)

    // per-thread column state (owner-private)
    float v4[JPT], minv4[JPT], tu4[JPT];
    unsigned mask = 0;
    #pragma unroll
    for (int k = 0; k < JPT; k++) { v4[k] = 0.f; minv4[k] = FLT_MAX; }

    // ---- row minima: one row per warp, packed (enc(value) << 32 | j) ----
    for (int i = warp + 1; i <= Tn; i += NWARP) {
        const float* crow = cost + (size_t)(i - 1) * Qn;
        float4 c4[8];
        #pragma unroll
        for (int s = 0; s < 7; s++)
            c4[s] = __ldg(reinterpret_cast<const float4*>(crow + s * 128 + lane * 4));
        c4[7] = (lane == 0) ? __ldg(reinterpret_cast<const float4*>(crow + 896))
                            : make_float4(FLT_MAX, FLT_MAX, FLT_MAX, FLT_MAX);
        unsigned long long best = ~0ull;
        #pragma unroll
        for (int s = 0; s < 8; s++) {
            int j0 = (s < 7) ? (s * 128 + lane * 4) : 896;
            #pragma unroll
            for (int k = 0; k < 4; k++) {
                unsigned long long e =
                    ((unsigned long long)enc_f((&c4[s].x)[k]) << 32) | (unsigned)(j0 + k + 1);
                if (e < best) best = e;
            }
        }
        #pragma unroll
        for (int s = 16; s; s >>= 1) {
            unsigned long long o = __shfl_down_sync(0xffffffffu, best, s);
            if (o < best) best = o;
        }
        if (lane == 0) {
            u[i] = dec_f((unsigned)(best >> 32));   // exact matrix entry -> tight edge
            rowq[i] = (int)(best & 0xffffffffu);
        }
    }
    __syncthreads();

    // ---- greedy assignment (serial, trivial) ----
    if (tid == 0) {
        for (int i = 1; i <= Tn; i++) {
            int j = rowq[i];
            if (p[j] == 0) { p[j] = i; s_assigned[i] = 1; }
            else s_assigned[i] = 0;
        }
    }
    __syncthreads();

    // ---- Dijkstra phases for free rows (deferred duals, register state) ----
    for (int i = 1; i <= Tn; i++) {
        if (s_assigned[i]) continue;
        if (tid == 0) p[0] = i;     // augment chain terminator (barrier-separated)

        int   i0 = i;
        float C  = 0.f;
        int   lastj1 = 0;
        int   it = 0;
        int   jfinal; float Cf;

        while (true) {
            int par = it & 1;
            float4 cr = make_float4(0.f, 0.f, 0.f, 0.f);
            if (valid) cr = __ldg(reinterpret_cast<const float4*>(
                                  cost + (size_t)(i0 - 1) * Qn + (jbase - 1)));
            float aC = u[i0] - C;

            unsigned benc = 0xFFFFFFFFu; int bj = 0x7FFFFFFF;
            if (valid) {
                #pragma unroll
                for (int k = 0; k < JPT; k++) {
                    if (!(mask & (1u << k))) {
                        float r = (&cr.x)[k] - aC - v4[k];
                        if (r < minv4[k]) { minv4[k] = r; way[jbase + k] = lastj1; }
                        unsigned e = enc_f(minv4[k]);
                        if (e < benc) { benc = e; bj = jbase + k; }
                    }
                }
            }
            unsigned m = __reduce_min_sync(0xffffffffu, benc);
            int cand = (benc == m) ? bj : 0x7FFFFFFF;
            int jm = __reduce_min_sync(0xffffffffu, cand);
            if (lane == 0) { s_wv[par][warp] = m; s_wi[par][warp] = jm; }
            __syncthreads();

            unsigned ge = s_wv[par][0]; int gj = s_wi[par][0];
            #pragma unroll
            for (int w = 1; w < NWARP; w++) {
                unsigned e2 = s_wv[par][w]; int j2 = s_wi[par][w];
                if (e2 < ge || (e2 == ge && j2 < gj)) { ge = e2; gj = j2; }
            }
            float Cn = dec_f(ge);
            int j1 = gj;
            int i0n = p[j1];                  // LDS broadcast
            if (i0n == 0) { jfinal = j1; Cf = Cn; break; }
            unsigned k1 = (unsigned)(j1 - jbase);
            if (valid && k1 < JPT) { mask |= 1u << k1; tu4[k1] = Cn; }  // owner-private
            lastj1 = j1; C = Cn; i0 = i0n; it++;
        }

        // apply duals (distinct rows per column => race-free) + reset state
        #pragma unroll
        for (int k = 0; k < JPT; k++) {
            if (mask & (1u << k)) {
                float dv = Cf - tu4[k];
                v4[k] -= dv;
                u[p[jbase + k]] += dv;
            }
            minv4[k] = FLT_MAX;
        }
        mask = 0;
        if (tid == 0) u[i] += Cf;            // via virtual column 0 (tu=0)
        __syncthreads();
        if (tid == 0) {                      // augment along alternating path
            int j0 = jfinal;
            while (j0) { int jp = way[j0]; p[j0] = p[jp]; j0 = jp; }
            s_assigned[i] = 1;
        }
        __syncthreads();
    }

    // ---- build qi per target in shared ----
    for (int j = tid + 1; j <= Qn; j += NTH) {
        int pi = p[j];
        if (pi > 0) rowq[pi] = j - 1;        // query index for target pi-1
    }
    __syncthreads();

    // ================= fused per-image loss =================
    int* tcl = way;                          // reuse [Qn+1] ints
    double l1 = 0.0, gsum = 0.0;
    if (tid < Tn) {
        int t = tid;
        int qi = rowq[t + 1];
        const float4 P = *reinterpret_cast<const float4*>(pb + (size_t)(b * Qn + qi) * 4);
        const float4 G = *reinterpret_cast<const float4*>(tb + (size_t)(b * Tn + t) * 4);
        double px = P.x, py = P.y, pw = P.z, ph = P.w;
        double gx = G.x, gy = G.y, gw = G.z, gh = G.w;
        l1 = fabs(px - gx) + fabs(py - gy) + fabs(pw - gw) + fabs(ph - gh);

        double p0 = px - 0.5 * pw, p1 = py - 0.5 * ph, p2 = px + 0.5 * pw, p3 = py + 0.5 * ph;
        double g0 = gx - 0.5 * gw, g1 = gy - 0.5 * gh, g2 = gx + 0.5 * gw, g3 = gy + 0.5 * gh;
        double a1 = (p2 - p0) * (p3 - p1);
        double a2 = (g2 - g0) * (g3 - g1);
        double iw = fmin(p2, g2) - fmax(p0, g0); iw = iw > 0.0 ? iw : 0.0;
        double ih = fmin(p3, g3) - fmax(p1, g1); ih = ih > 0.0 ? ih : 0.0;
        double inter = iw * ih;
        double uni = a1 + a2 - inter;
        double iou = inter / uni;
        double cw = fmax(p2, g2) - fmin(p0, g0);
        double ch = fmax(p3, g3) - fmin(p1, g1);
        double ac = cw * ch;
        double giou = iou - (ac - uni) / ac;
        gsum = 1.0 - giou;
    }

    for (int q = tid; q < Qn; q += NTH) tcl[q] = NUM_CLASSES;
    __syncthreads();
    if (tid < Tn) tcl[rowq[tid + 1]] = lab[b * Tn + tid];
    __syncthreads();

    double wn = 0.0, ws = 0.0;
    for (int q = tid; q < Qn; q += NTH) {
        int c = tcl[q];
        double w = (c == NUM_CLASSES) ? 0.05 : 1.0;
        double nll = (double)g_lse[b * Qn + q] - (double)pc[(size_t)(b * Qn + q) * C1 + c];
        wn += w * nll; ws += w;
    }

    sred[tid] = l1;   __syncthreads();
    for (int s = NTH / 2; s; s >>= 1) { if (tid < s) sred[tid] += sred[tid + s]; __syncthreads(); }
    double l1t = sred[0]; __syncthreads();
    sred[tid] = gsum; __syncthreads();
    for (int s = NTH / 2; s; s >>= 1) { if (tid < s) sred[tid] += sred[tid + s]; __syncthreads(); }
    double gst = sred[0]; __syncthreads();
    sred[tid] = wn;   __syncthreads();
    for (int s = NTH / 2; s; s >>= 1) { if (tid < s) sred[tid] += sred[tid + s]; __syncthreads(); }
    double wnt = sred[0]; __syncthreads();
    sred[tid] = ws;   __syncthreads();
    for (int s = NTH / 2; s; s >>= 1) { if (tid < s) sred[tid] += sred[tid + s]; __syncthreads(); }
    double wst = sred[0]; __syncthreads();

    if (tid == 0) {
        double bbox = 5.0 * (l1t / (Tn * 4.0)) + 2.0 * (gst / Tn);
        g_partial[b] = bbox + wnt / wst;
        __threadfence();
        int t = atomicAdd(&g_ctr, 1);
        s_last = (t == Bn - 1);
    }
    __syncthreads();

    if (s_last) {
        double val = (tid < Bn) ? ((volatile double*)g_partial)[tid] : 0.0;
        sred[tid] = val; __syncthreads();
        for (int s = NTH / 2; s; s >>= 1) { if (tid < s) sred[tid] += sred[tid + s]; __syncthreads(); }
        if (tid == 0) {
            out[0] = (float)(sred[0] / (double)(Bn * Tn));
            g_ctr = 0;                      // restore for next graph replay
        }
    }
}

extern "C" void kernel_launch(void* const* d_in, const int* in_sizes, int n_in,
                              void* d_out, int out_size)
{
    const float* pc  = (const float*)d_in[0];   // predicted_class [64,900,14]
    const float* pb  = (const float*)d_in[1];   // predicted_bbox  [64,900,4]
    const int*   lab = (const int*)  d_in[2];   // target_labels   [64,128]
    const float* tb  = (const float*)d_in[3];   // target_boxes    [64,128,4]
    float* out = (float*)d_out;

    dim3 cgrid((Qn + NT - 1) / NT, Bn, TSPLIT);
    cost_kernel<<<cgrid, NT>>>(pc, pb, lab, tb);
    hungarian_loss_kernel<<<Bn, NTH>>>(pc, pb, lab, tb, out);
}